// round 8
// baseline (speedup 1.0000x reference)
#include <cuda_runtime.h>
#include <math.h>

#define H     128
#define PPB   64        // paths per block
#define NTH   256       // threads per block (8 warps -> 2 per SMSP)
#define WS    136       // weight row stride (floats)
#define BS    68        // activation buffer row stride (64 paths + 4 pad)

// ---- shared memory layout (floats) ----
// fw2s: H*WS = 17408 ; gw2s: H*WS = 17408
// buf1: H*BS =  8704 ; buf2: H*BS =  8704  (corrp [32*64*2=4096] aliases buf2)
// red_sm: 256 ; small arrays ~2300
#define SMEM_FLOATS 54792
#define SMEM_BYTES  (SMEM_FLOATS * 4)

__device__ __forceinline__ float sigmoidf_(float x) {
    return __fdividef(1.0f, 1.0f + __expf(-x));
}
__device__ __forceinline__ float siluf_(float x) {
    return x * sigmoidf_(x);
}

// Forward GEMM: C[j][p] = act( sum_k A[k][p] * W[k][j] + b[j] )
// 256 threads: 8 p-groups (8 paths) x 32 j-groups (4 outputs) => 32 acc/thread
template<bool DOSILU>
__device__ __forceinline__ void gemm_fwd(const float* __restrict__ A,
                                         const float* __restrict__ W,
                                         const float* __restrict__ b,
                                         float* __restrict__ C, int tid)
{
    const int pg = tid & 7, jg = tid >> 3;     // jg 0..31
    const int p8 = pg * 8, j4 = jg * 4;
    float acc[4][8];
#pragma unroll
    for (int a = 0; a < 4; a++)
#pragma unroll
        for (int c = 0; c < 8; c++) acc[a][c] = 0.0f;

#pragma unroll 4
    for (int k = 0; k < H; k++) {
        float4 a0 = *(const float4*)&A[k * BS + p8];
        float4 a1 = *(const float4*)&A[k * BS + p8 + 4];
        float4 w  = *(const float4*)&W[k * WS + j4];
        float av[8] = {a0.x, a0.y, a0.z, a0.w, a1.x, a1.y, a1.z, a1.w};
        float wv[4] = {w.x, w.y, w.z, w.w};
#pragma unroll
        for (int jj = 0; jj < 4; jj++)
#pragma unroll
            for (int pp = 0; pp < 8; pp++)
                acc[jj][pp] = fmaf(wv[jj], av[pp], acc[jj][pp]);
    }

#pragma unroll
    for (int jj = 0; jj < 4; jj++) {
        float bb = b[j4 + jj];
        float r[8];
#pragma unroll
        for (int pp = 0; pp < 8; pp++) {
            float z = acc[jj][pp] + bb;
            r[pp] = DOSILU ? siluf_(z) : z;
        }
        *(float4*)&C[(j4 + jj) * BS + p8]     = make_float4(r[0], r[1], r[2], r[3]);
        *(float4*)&C[(j4 + jj) * BS + p8 + 4] = make_float4(r[4], r[5], r[6], r[7]);
    }
}

// Backward GEMM + fused epilogue:
//   dh1[p][k2] = sum_j Dz[j][p] * Wg[k2][j]
//   dz1 = dh1 * silu'(z1(p,k2)),  corr partials into corrp[kg][p][d]
// 256 threads: 8 p-groups x 32 k-groups (4 k each)
__device__ __forceinline__ void gemm_bwd_epi(const float* __restrict__ Dz,
                                             const float* __restrict__ Wg,
                                             const float* __restrict__ gw1s,
                                             const float* __restrict__ gb1s,
                                             const float* __restrict__ ysm,
                                             float* __restrict__ corrp, int tid)
{
    const int pg = tid & 7, kg = tid >> 3;     // kg 0..31
    const int p8 = pg * 8, k4 = kg * 4;
    float acc[4][8];
#pragma unroll
    for (int a = 0; a < 4; a++)
#pragma unroll
        for (int c = 0; c < 8; c++) acc[a][c] = 0.0f;

#pragma unroll 4
    for (int j = 0; j < H; j++) {
        float4 a0 = *(const float4*)&Dz[j * BS + p8];
        float4 a1 = *(const float4*)&Dz[j * BS + p8 + 4];
        float av[8] = {a0.x, a0.y, a0.z, a0.w, a1.x, a1.y, a1.z, a1.w};
        float wv[4];
#pragma unroll
        for (int kk = 0; kk < 4; kk++) wv[kk] = Wg[(k4 + kk) * WS + j];
#pragma unroll
        for (int kk = 0; kk < 4; kk++)
#pragma unroll
            for (int pp = 0; pp < 8; pp++)
                acc[kk][pp] = fmaf(wv[kk], av[pp], acc[kk][pp]);
    }

    // epilogue: dz1 = dh1 * silu'(z1), z1 recomputed from y
    float w0[4], w1[4], bb[4];
#pragma unroll
    for (int kk = 0; kk < 4; kk++) {
        w0[kk] = gw1s[k4 + kk];
        w1[kk] = gw1s[H + k4 + kk];
        bb[kk] = gb1s[k4 + kk];
    }
#pragma unroll
    for (int pp = 0; pp < 8; pp++) {
        int p = p8 + pp;
        float ya = ysm[p * 2], yb = ysm[p * 2 + 1];
        float c0 = 0.0f, c1 = 0.0f;
#pragma unroll
        for (int kk = 0; kk < 4; kk++) {
            float z1 = fmaf(ya, w0[kk], fmaf(yb, w1[kk], bb[kk]));
            float s  = sigmoidf_(z1);
            float spr = s * (1.0f + z1 * (1.0f - s));
            float dz1 = acc[kk][pp] * spr;
            c0 = fmaf(dz1, w0[kk], c0);
            c1 = fmaf(dz1, w1[kk], c1);
        }
        corrp[(kg * PPB + p) * 2]     = c0;
        corrp[(kg * PPB + p) * 2 + 1] = c1;
    }
}

extern "C" __global__ void __launch_bounds__(NTH, 1)
sde_milstein_kernel(const float* __restrict__ y0, const float* __restrict__ ts,
                    const float* __restrict__ dW,
                    const float* __restrict__ fw1, const float* __restrict__ fb1,
                    const float* __restrict__ fw2, const float* __restrict__ fb2,
                    const float* __restrict__ fw3, const float* __restrict__ fb3,
                    const float* __restrict__ gw1, const float* __restrict__ gb1,
                    const float* __restrict__ gw2, const float* __restrict__ gb2,
                    const float* __restrict__ gw3, const float* __restrict__ gb3,
                    float* __restrict__ out, int T, int NP)
{
    extern __shared__ float sm[];
    float* fw2s = sm;                      // 17408
    float* gw2s = fw2s + H * WS;           // 17408
    float* buf1 = gw2s + H * WS;           // 8704
    float* buf2 = buf1 + H * BS;           // 8704
    float* corrp = buf2;                   // aliases buf2 (free after P7)
    float* red_sm = buf2 + H * BS;         // 256
    float* fw1s = red_sm + NTH;            // 384   [i*128+k]
    float* fb1s = fw1s + 3 * H;            // 128
    float* fb2s = fb1s + H;                // 128
    float* fw3s = fb2s + H;                // 256   [j*2+d]
    float* fb3s = fw3s + H * 2;            // 4
    float* gw1s = fb3s + 4;                // 256   [i*128+k]
    float* gb1s = gw1s + 2 * H;            // 128
    float* gb2s = gb1s + H;                // 128
    float* gw3s = gb2s + H;                // 256   [j*2+d]
    float* gb3s = gw3s + H * 2;            // 4
    float* ysm  = gb3s + 4;                // 128   [p*2+d]
    float* f_sm = ysm + PPB * 2;           // 128
    float* g_sm = f_sm + PPB * 2;          // 128
    float* dw_sm = g_sm + PPB * 2;         // 128
    float* dr_sm = dw_sm + PPB * 2;        // 128

    const int tid = threadIdx.x;
    const int p0g = blockIdx.x * PPB;

    // ---- load weights into shared ----
    for (int i = tid; i < H * H; i += NTH) {
        int k = i >> 7, j = i & 127;
        fw2s[k * WS + j] = fw2[i];
        gw2s[k * WS + j] = gw2[i];
    }
    for (int i = tid; i < 3 * H; i += NTH) fw1s[i] = fw1[i];
    for (int i = tid; i < 2 * H; i += NTH) {
        gw1s[i] = gw1[i];
        fw3s[i] = fw3[i];
        gw3s[i] = gw3[i];
    }
    for (int i = tid; i < H; i += NTH) {
        fb1s[i] = fb1[i]; fb2s[i] = fb2[i];
        gb1s[i] = gb1[i]; gb2s[i] = gb2[i];
    }
    if (tid < 2) { fb3s[tid] = fb3[tid]; gb3s[tid] = gb3[tid]; }

    // ---- init state + write t=0 output ----
    if (tid < 2 * PPB) {
        int p = tid >> 1, d = tid & 1;
        float v = y0[(size_t)(p0g) * 2 + tid];
        ysm[tid] = v;
        out[(size_t)(p0g + p) * (size_t)(T * 2) + d] = v;
    }
    __syncthreads();

    const int pA = tid & 63;     // path for elementwise-over-k phases
    const int kA = tid >> 6;     // starting k (0..3), step 4

    for (int t = 0; t < T - 1; ++t) {
        float dt = ts[t + 1] - ts[t];
        float sqdt = sqrtf(dt);

        // P1: drift layer1 -> buf1 = silu([y, spread] @ fw1 + fb1), transposed [k][p]
        {
            float ya = ysm[pA * 2], yb = ysm[pA * 2 + 1], yc = ya - yb;
#pragma unroll 4
            for (int k = kA; k < H; k += 4) {
                float z = fb1s[k];
                z = fmaf(ya, fw1s[k], z);
                z = fmaf(yb, fw1s[H + k], z);
                z = fmaf(yc, fw1s[2 * H + k], z);
                buf1[k * BS + pA] = siluf_(z);
            }
        }
        __syncthreads();

        // G1: h2f = silu(h1f @ fw2 + fb2) -> buf2
        gemm_fwd<true>(buf1, fw2s, fb2s, buf2, tid);
        __syncthreads();

        // P3 (warps 0-3): f = h2f @ fw3 + fb3  ||  P4 (warps 4-7): diffusion L1 -> buf1
        if (tid < 128) {
            int p = tid >> 1, d = tid & 1;
            float a0 = 0.0f, a1 = 0.0f;
#pragma unroll 8
            for (int j = 0; j < H; j += 2) {
                a0 = fmaf(buf2[j * BS + p],       fw3s[j * 2 + d],       a0);
                a1 = fmaf(buf2[(j + 1) * BS + p], fw3s[(j + 1) * 2 + d], a1);
            }
            f_sm[tid] = a0 + a1 + fb3s[d];
        } else {
            int pB = tid & 63, kB = (tid >> 6) & 1;   // 0 or 1, step 2
            float ya = ysm[pB * 2], yb = ysm[pB * 2 + 1];
#pragma unroll 4
            for (int k = kB; k < H; k += 2) {
                float z = fmaf(ya, gw1s[k], fmaf(yb, gw1s[H + k], gb1s[k]));
                buf1[k * BS + pB] = siluf_(z);
            }
        }
        __syncthreads();

        // G2: z2g = h1g @ gw2 + gb2 (PRE-activation kept for backward) -> buf2
        gemm_fwd<false>(buf1, gw2s, gb2s, buf2, tid);
        __syncthreads();

        // P6a: partial head sums, split j-range across 2 threads per (p,d)
        {
            int idx = tid & 127, half = tid >> 7;
            int p = idx >> 1, d = idx & 1;
            int j0 = half * 64;
            float a0 = 0.0f;
#pragma unroll 4
            for (int j = j0; j < j0 + 64; j++)
                a0 = fmaf(siluf_(buf2[j * BS + p]), gw3s[j * 2 + d], a0);
            red_sm[tid] = a0;
        }
        __syncthreads();

        // P6b: g = clip(softplus(raw)), Milstein cotangent draw
        if (tid < 128) {
            int p = tid >> 1, d = tid & 1;
            float raw = red_sm[tid] + red_sm[tid + 128] + gb3s[d];
            float e  = __expf(raw);
            float sp = (raw > 15.0f) ? raw : log1pf(e);
            float g  = fminf(fmaxf(sp, 1e-4f), 5.0f);
            float dwv = dW[((size_t)t * (size_t)NP + (p0g + p)) * 2 + d] * sqdt;
            float v   = 0.5f * (dwv * dwv - dt);
            float sig = __fdividef(e, 1.0f + e);              // sigmoid(raw)
            float m   = (sp > 1e-4f && sp < 5.0f) ? 1.0f : 0.0f;
            g_sm[tid]  = g;
            dw_sm[tid] = dwv;
            dr_sm[tid] = v * g * sig * m;
        }
        __syncthreads();

        // P7: dz2 = (draw @ gw3^T) * silu'(z2g) -> buf1
        {
            float r0 = dr_sm[pA * 2], r1 = dr_sm[pA * 2 + 1];
#pragma unroll 4
            for (int k = kA; k < H; k += 4) {
                float z = buf2[k * BS + pA];
                float s = sigmoidf_(z);
                float spr = s * (1.0f + z * (1.0f - s));
                float dh2 = fmaf(r0, gw3s[k * 2], r1 * gw3s[k * 2 + 1]);
                buf1[k * BS + pA] = dh2 * spr;
            }
        }
        __syncthreads();

        // G3: dh1 = dz2 @ gw2^T, fused dz1 + corr partials -> corrp (aliases buf2)
        gemm_bwd_epi(buf1, gw2s, gw1s, gb1s, ysm, corrp, tid);
        __syncthreads();

        // P9a: partial corr reduction (16 groups per thread)
        {
            int idx = tid & 127, half = tid >> 7;
            int p = idx >> 1, d = idx & 1;
            float c = 0.0f;
#pragma unroll
            for (int kg = half * 16; kg < half * 16 + 16; kg++)
                c += corrp[(kg * PPB + p) * 2 + d];
            red_sm[tid] = c;
        }
        __syncthreads();

        // P9b: Milstein update, write output
        if (tid < 128) {
            int p = tid >> 1, d = tid & 1;
            float c = red_sm[tid] + red_sm[tid + 128];
            float yn = ysm[tid] + f_sm[tid] * dt + g_sm[tid] * dw_sm[tid] + c;
            ysm[tid] = yn;
            out[(size_t)(p0g + p) * (size_t)(T * 2) + (size_t)(t + 1) * 2 + d] = yn;
        }
        __syncthreads();
    }
}

extern "C" void kernel_launch(void* const* d_in, const int* in_sizes, int n_in,
                              void* d_out, int out_size)
{
    const float* y0  = (const float*)d_in[0];
    const float* ts  = (const float*)d_in[1];
    const float* dW  = (const float*)d_in[2];
    const float* fw1 = (const float*)d_in[3];
    const float* fb1 = (const float*)d_in[4];
    const float* fw2 = (const float*)d_in[5];
    const float* fb2 = (const float*)d_in[6];
    const float* fw3 = (const float*)d_in[7];
    const float* fb3 = (const float*)d_in[8];
    const float* gw1 = (const float*)d_in[9];
    const float* gb1 = (const float*)d_in[10];
    const float* gw2 = (const float*)d_in[11];
    const float* gb2 = (const float*)d_in[12];
    const float* gw3 = (const float*)d_in[13];
    const float* gb3 = (const float*)d_in[14];
    float* out = (float*)d_out;

    int T  = in_sizes[1];          // 512
    int NP = in_sizes[0] / 2;      // 8192
    int nb = NP / PPB;             // 128 blocks

    cudaFuncSetAttribute(sde_milstein_kernel,
                         cudaFuncAttributeMaxDynamicSharedMemorySize, SMEM_BYTES);

    sde_milstein_kernel<<<nb, NTH, SMEM_BYTES>>>(
        y0, ts, dW, fw1, fb1, fw2, fb2, fw3, fb3,
        gw1, gb1, gw2, gb2, gw3, gb3, out, T, NP);
}

// round 9
// speedup vs baseline: 1.0292x; 1.0292x over previous
#include <cuda_runtime.h>
#include <math.h>

#define H     128
#define PPB   64        // paths per block
#define NTH   256       // threads per block (8 warps -> 2 per SMSP)
#define WS    136       // weight row stride (floats)
#define BS    68        // activation buffer row stride (64 paths + 4 pad)

// ---- shared memory layout (floats) ----
// fw2s: H*WS = 17408 ; gw2s: H*WS = 17408
// buf1: H*BS =  8704 ; buf2: H*BS =  8704  (corrp [32*64*2=4096] aliases buf2)
// red_sm: 256 ; small arrays ~2300
#define SMEM_FLOATS 54792
#define SMEM_BYTES  (SMEM_FLOATS * 4)

typedef unsigned long long ull;

// packed fp32x2 FMA (Blackwell sm_103a): acc = a*b + acc, two lanes per reg-pair
#define FMA2(acc, a, b) \
    asm("fma.rn.f32x2 %0, %1, %2, %0;" : "+l"(acc) : "l"(a), "l"(b))
#define PACK2(out, lo, hi) \
    asm("mov.b64 %0, {%1, %2};" : "=l"(out) : "f"(lo), "f"(hi))
#define UNPACK2(lo, hi, in) \
    asm("mov.b64 {%0, %1}, %2;" : "=f"(lo), "=f"(hi) : "l"(in))

__device__ __forceinline__ float sigmoidf_(float x) {
    return __fdividef(1.0f, 1.0f + __expf(-x));
}
__device__ __forceinline__ float siluf_(float x) {
    return x * sigmoidf_(x);
}

// Forward GEMM: C[j][p] = act( sum_k A[k][p] * W[k][j] + b[j] )
// 256 threads: 8 p-groups (8 paths, packed as 4 f32x2) x 32 j-groups (4 outputs)
template<bool DOSILU>
__device__ __forceinline__ void gemm_fwd(const float* __restrict__ A,
                                         const float* __restrict__ W,
                                         const float* __restrict__ b,
                                         float* __restrict__ C, int tid)
{
    const int pg = tid & 7, jg = tid >> 3;     // jg 0..31
    const int p8 = pg * 8, j4 = jg * 4;
    ull acc[4][4];                              // [jj][pair]
#pragma unroll
    for (int a = 0; a < 4; a++)
#pragma unroll
        for (int c = 0; c < 4; c++) acc[a][c] = 0ULL;   // two packed +0.0f

#pragma unroll 4
    for (int k = 0; k < H; k++) {
        // 8 consecutive path values -> 4 packed f32x2 (no pack cost)
        ulonglong2 a01 = *(const ulonglong2*)&A[k * BS + p8];
        ulonglong2 a23 = *(const ulonglong2*)&A[k * BS + p8 + 4];
        ull ap[4] = {a01.x, a01.y, a23.x, a23.y};
        float4 w = *(const float4*)&W[k * WS + j4];
        float wv[4] = {w.x, w.y, w.z, w.w};
#pragma unroll
        for (int jj = 0; jj < 4; jj++) {
            ull wp; PACK2(wp, wv[jj], wv[jj]);
#pragma unroll
            for (int q = 0; q < 4; q++)
                FMA2(acc[jj][q], wp, ap[q]);
        }
    }

#pragma unroll
    for (int jj = 0; jj < 4; jj++) {
        float bb = b[j4 + jj];
        float r[8];
#pragma unroll
        for (int q = 0; q < 4; q++)
            UNPACK2(r[2 * q], r[2 * q + 1], acc[jj][q]);
#pragma unroll
        for (int pp = 0; pp < 8; pp++) {
            float z = r[pp] + bb;
            r[pp] = DOSILU ? siluf_(z) : z;
        }
        *(float4*)&C[(j4 + jj) * BS + p8]     = make_float4(r[0], r[1], r[2], r[3]);
        *(float4*)&C[(j4 + jj) * BS + p8 + 4] = make_float4(r[4], r[5], r[6], r[7]);
    }
}

// Backward GEMM + fused epilogue:
//   dh1[p][k] = sum_j Dz[j][p] * Wg[k][j]
//   dz1 = dh1 * silu'(z1(p,k)),  corr partials into corrp[kg][p][d]
// 256 threads: 8 p-groups x 32 k-groups. Each k-group owns STRIDED k-set
// {kg, kg+32, kg+64, kg+96} so per-LDS-inst addresses are k-consecutive
// (bank stride 8 -> conflict-free), unlike consecutive-k (stride 4*WS = 0 mod 32).
__device__ __forceinline__ void gemm_bwd_epi(const float* __restrict__ Dz,
                                             const float* __restrict__ Wg,
                                             const float* __restrict__ gw1s,
                                             const float* __restrict__ gb1s,
                                             const float* __restrict__ ysm,
                                             float* __restrict__ corrp, int tid)
{
    const int pg = tid & 7, kg = tid >> 3;     // kg 0..31
    const int p8 = pg * 8;
    ull acc[4][4];                              // [m][pair], k = kg + 32*m
#pragma unroll
    for (int a = 0; a < 4; a++)
#pragma unroll
        for (int c = 0; c < 4; c++) acc[a][c] = 0ULL;

#pragma unroll 4
    for (int j = 0; j < H; j++) {
        ulonglong2 a01 = *(const ulonglong2*)&Dz[j * BS + p8];
        ulonglong2 a23 = *(const ulonglong2*)&Dz[j * BS + p8 + 4];
        ull ap[4] = {a01.x, a01.y, a23.x, a23.y};
#pragma unroll
        for (int m = 0; m < 4; m++) {
            float w = Wg[(kg + 32 * m) * WS + j];
            ull wp; PACK2(wp, w, w);
#pragma unroll
            for (int q = 0; q < 4; q++)
                FMA2(acc[m][q], wp, ap[q]);
        }
    }

    // epilogue: dz1 = dh1 * silu'(z1), z1 recomputed from y
    float w0[4], w1[4], bb[4];
#pragma unroll
    for (int m = 0; m < 4; m++) {
        int k = kg + 32 * m;
        w0[m] = gw1s[k];
        w1[m] = gw1s[H + k];
        bb[m] = gb1s[k];
    }
    float dh1[4][8];
#pragma unroll
    for (int m = 0; m < 4; m++)
#pragma unroll
        for (int q = 0; q < 4; q++)
            UNPACK2(dh1[m][2 * q], dh1[m][2 * q + 1], acc[m][q]);

#pragma unroll
    for (int pp = 0; pp < 8; pp++) {
        int p = p8 + pp;
        float ya = ysm[p * 2], yb = ysm[p * 2 + 1];
        float c0 = 0.0f, c1 = 0.0f;
#pragma unroll
        for (int m = 0; m < 4; m++) {
            float z1 = fmaf(ya, w0[m], fmaf(yb, w1[m], bb[m]));
            float s  = sigmoidf_(z1);
            float spr = s * (1.0f + z1 * (1.0f - s));
            float dz1 = dh1[m][pp] * spr;
            c0 = fmaf(dz1, w0[m], c0);
            c1 = fmaf(dz1, w1[m], c1);
        }
        corrp[(kg * PPB + p) * 2]     = c0;
        corrp[(kg * PPB + p) * 2 + 1] = c1;
    }
}

extern "C" __global__ void __launch_bounds__(NTH, 1)
sde_milstein_kernel(const float* __restrict__ y0, const float* __restrict__ ts,
                    const float* __restrict__ dW,
                    const float* __restrict__ fw1, const float* __restrict__ fb1,
                    const float* __restrict__ fw2, const float* __restrict__ fb2,
                    const float* __restrict__ fw3, const float* __restrict__ fb3,
                    const float* __restrict__ gw1, const float* __restrict__ gb1,
                    const float* __restrict__ gw2, const float* __restrict__ gb2,
                    const float* __restrict__ gw3, const float* __restrict__ gb3,
                    float* __restrict__ out, int T, int NP)
{
    extern __shared__ float sm[];
    float* fw2s = sm;                      // 17408
    float* gw2s = fw2s + H * WS;           // 17408
    float* buf1 = gw2s + H * WS;           // 8704
    float* buf2 = buf1 + H * BS;           // 8704
    float* corrp = buf2;                   // aliases buf2 (free after P7)
    float* red_sm = buf2 + H * BS;         // 256
    float* fw1s = red_sm + NTH;            // 384   [i*128+k]
    float* fb1s = fw1s + 3 * H;            // 128
    float* fb2s = fb1s + H;                // 128
    float* fw3s = fb2s + H;                // 256   [j*2+d]
    float* fb3s = fw3s + H * 2;            // 4
    float* gw1s = fb3s + 4;                // 256   [i*128+k]
    float* gb1s = gw1s + 2 * H;            // 128
    float* gb2s = gb1s + H;                // 128
    float* gw3s = gb2s + H;                // 256   [j*2+d]
    float* gb3s = gw3s + H * 2;            // 4
    float* ysm  = gb3s + 4;                // 128   [p*2+d]
    float* f_sm = ysm + PPB * 2;           // 128
    float* g_sm = f_sm + PPB * 2;          // 128
    float* dw_sm = g_sm + PPB * 2;         // 128
    float* dr_sm = dw_sm + PPB * 2;        // 128

    const int tid = threadIdx.x;
    const int p0g = blockIdx.x * PPB;

    // ---- load weights into shared ----
    for (int i = tid; i < H * H; i += NTH) {
        int k = i >> 7, j = i & 127;
        fw2s[k * WS + j] = fw2[i];
        gw2s[k * WS + j] = gw2[i];
    }
    for (int i = tid; i < 3 * H; i += NTH) fw1s[i] = fw1[i];
    for (int i = tid; i < 2 * H; i += NTH) {
        gw1s[i] = gw1[i];
        fw3s[i] = fw3[i];
        gw3s[i] = gw3[i];
    }
    for (int i = tid; i < H; i += NTH) {
        fb1s[i] = fb1[i]; fb2s[i] = fb2[i];
        gb1s[i] = gb1[i]; gb2s[i] = gb2[i];
    }
    if (tid < 2) { fb3s[tid] = fb3[tid]; gb3s[tid] = gb3[tid]; }

    // ---- init state + write t=0 output ----
    if (tid < 2 * PPB) {
        int p = tid >> 1, d = tid & 1;
        float v = y0[(size_t)(p0g) * 2 + tid];
        ysm[tid] = v;
        out[(size_t)(p0g + p) * (size_t)(T * 2) + d] = v;
    }
    __syncthreads();

    const int pA = tid & 63;     // path for elementwise-over-k phases
    const int kA = tid >> 6;     // starting k (0..3), step 4

    for (int t = 0; t < T - 1; ++t) {
        float dt = ts[t + 1] - ts[t];
        float sqdt = sqrtf(dt);

        // P1: drift layer1 -> buf1 = silu([y, spread] @ fw1 + fb1), transposed [k][p]
        {
            float ya = ysm[pA * 2], yb = ysm[pA * 2 + 1], yc = ya - yb;
#pragma unroll 4
            for (int k = kA; k < H; k += 4) {
                float z = fb1s[k];
                z = fmaf(ya, fw1s[k], z);
                z = fmaf(yb, fw1s[H + k], z);
                z = fmaf(yc, fw1s[2 * H + k], z);
                buf1[k * BS + pA] = siluf_(z);
            }
        }
        __syncthreads();

        // G1: h2f = silu(h1f @ fw2 + fb2) -> buf2
        gemm_fwd<true>(buf1, fw2s, fb2s, buf2, tid);
        __syncthreads();

        // P3 (warps 0-3): f = h2f @ fw3 + fb3  ||  P4 (warps 4-7): diffusion L1 -> buf1
        if (tid < 128) {
            int p = tid >> 1, d = tid & 1;
            float a0 = 0.0f, a1 = 0.0f;
#pragma unroll 8
            for (int j = 0; j < H; j += 2) {
                a0 = fmaf(buf2[j * BS + p],       fw3s[j * 2 + d],       a0);
                a1 = fmaf(buf2[(j + 1) * BS + p], fw3s[(j + 1) * 2 + d], a1);
            }
            f_sm[tid] = a0 + a1 + fb3s[d];
        } else {
            int pB = tid & 63, kB = (tid >> 6) & 1;   // 0 or 1, step 2
            float ya = ysm[pB * 2], yb = ysm[pB * 2 + 1];
#pragma unroll 4
            for (int k = kB; k < H; k += 2) {
                float z = fmaf(ya, gw1s[k], fmaf(yb, gw1s[H + k], gb1s[k]));
                buf1[k * BS + pB] = siluf_(z);
            }
        }
        __syncthreads();

        // G2: z2g = h1g @ gw2 + gb2 (PRE-activation kept for backward) -> buf2
        gemm_fwd<false>(buf1, gw2s, gb2s, buf2, tid);
        __syncthreads();

        // P6a: partial head sums, split j-range across 2 threads per (p,d)
        {
            int idx = tid & 127, half = tid >> 7;
            int p = idx >> 1, d = idx & 1;
            int j0 = half * 64;
            float a0 = 0.0f;
#pragma unroll 4
            for (int j = j0; j < j0 + 64; j++)
                a0 = fmaf(siluf_(buf2[j * BS + p]), gw3s[j * 2 + d], a0);
            red_sm[tid] = a0;
        }
        __syncthreads();

        // P6b: g = clip(softplus(raw)), Milstein cotangent draw
        if (tid < 128) {
            int p = tid >> 1, d = tid & 1;
            float raw = red_sm[tid] + red_sm[tid + 128] + gb3s[d];
            float e  = __expf(raw);
            float sp = (raw > 15.0f) ? raw : log1pf(e);
            float g  = fminf(fmaxf(sp, 1e-4f), 5.0f);
            float dwv = dW[((size_t)t * (size_t)NP + (p0g + p)) * 2 + d] * sqdt;
            float v   = 0.5f * (dwv * dwv - dt);
            float sig = __fdividef(e, 1.0f + e);              // sigmoid(raw)
            float m   = (sp > 1e-4f && sp < 5.0f) ? 1.0f : 0.0f;
            g_sm[tid]  = g;
            dw_sm[tid] = dwv;
            dr_sm[tid] = v * g * sig * m;
        }
        __syncthreads();

        // P7: dz2 = (draw @ gw3^T) * silu'(z2g) -> buf1
        {
            float r0 = dr_sm[pA * 2], r1 = dr_sm[pA * 2 + 1];
#pragma unroll 4
            for (int k = kA; k < H; k += 4) {
                float z = buf2[k * BS + pA];
                float s = sigmoidf_(z);
                float spr = s * (1.0f + z * (1.0f - s));
                float dh2 = fmaf(r0, gw3s[k * 2], r1 * gw3s[k * 2 + 1]);
                buf1[k * BS + pA] = dh2 * spr;
            }
        }
        __syncthreads();

        // G3: dh1 = dz2 @ gw2^T, fused dz1 + corr partials -> corrp (aliases buf2)
        gemm_bwd_epi(buf1, gw2s, gw1s, gb1s, ysm, corrp, tid);
        __syncthreads();

        // P9a: partial corr reduction (16 groups per thread)
        {
            int idx = tid & 127, half = tid >> 7;
            int p = idx >> 1, d = idx & 1;
            float c = 0.0f;
#pragma unroll
            for (int kg = half * 16; kg < half * 16 + 16; kg++)
                c += corrp[(kg * PPB + p) * 2 + d];
            red_sm[tid] = c;
        }
        __syncthreads();

        // P9b: Milstein update, write output
        if (tid < 128) {
            int p = tid >> 1, d = tid & 1;
            float c = red_sm[tid] + red_sm[tid + 128];
            float yn = ysm[tid] + f_sm[tid] * dt + g_sm[tid] * dw_sm[tid] + c;
            ysm[tid] = yn;
            out[(size_t)(p0g + p) * (size_t)(T * 2) + (size_t)(t + 1) * 2 + d] = yn;
        }
        __syncthreads();
    }
}

extern "C" void kernel_launch(void* const* d_in, const int* in_sizes, int n_in,
                              void* d_out, int out_size)
{
    const float* y0  = (const float*)d_in[0];
    const float* ts  = (const float*)d_in[1];
    const float* dW  = (const float*)d_in[2];
    const float* fw1 = (const float*)d_in[3];
    const float* fb1 = (const float*)d_in[4];
    const float* fw2 = (const float*)d_in[5];
    const float* fb2 = (const float*)d_in[6];
    const float* fw3 = (const float*)d_in[7];
    const float* fb3 = (const float*)d_in[8];
    const float* gw1 = (const float*)d_in[9];
    const float* gb1 = (const float*)d_in[10];
    const float* gw2 = (const float*)d_in[11];
    const float* gb2 = (const float*)d_in[12];
    const float* gw3 = (const float*)d_in[13];
    const float* gb3 = (const float*)d_in[14];
    float* out = (float*)d_out;

    int T  = in_sizes[1];          // 512
    int NP = in_sizes[0] / 2;      // 8192
    int nb = NP / PPB;             // 128 blocks

    cudaFuncSetAttribute(sde_milstein_kernel,
                         cudaFuncAttributeMaxDynamicSharedMemorySize, SMEM_BYTES);

    sde_milstein_kernel<<<nb, NTH, SMEM_BYTES>>>(
        y0, ts, dW, fw1, fb1, fw2, fb2, fw3, fb3,
        gw1, gb1, gw2, gb2, gw3, gb3, out, T, NP);
}

// round 10
// speedup vs baseline: 1.1047x; 1.0734x over previous
#include <cuda_runtime.h>
#include <math.h>

#define H     128
#define PPB   64        // paths per block
#define NTH   128       // threads per block (1 warp per SMSP, max ILP per thread)
#define WS    136       // weight row stride (floats)
#define BS    68        // activation buffer row stride (64 paths + 4 pad)

// ---- shared memory layout (floats): total 56584 = 226336 B ----
#define SMEM_FLOATS 56584
#define SMEM_BYTES  (SMEM_FLOATS * 4)

typedef unsigned long long ull;

// packed fp32x2 FMA (Blackwell sm_103a): acc = a*b + acc, two fp32 lanes per 64-bit pair
#define FMA2(acc, a, b) \
    asm("fma.rn.f32x2 %0, %1, %2, %0;" : "+l"(acc) : "l"(a), "l"(b))
#define PACK2(out, lo, hi) \
    asm("mov.b64 %0, {%1, %2};" : "=l"(out) : "f"(lo), "f"(hi))
#define UNPACK2(lo, hi, in) \
    asm("mov.b64 {%0, %1}, %2;" : "=f"(lo), "=f"(hi) : "l"(in))

__device__ __forceinline__ float sigmoidf_(float x) {
    return __fdividef(1.0f, 1.0f + __expf(-x));
}
__device__ __forceinline__ float siluf_(float x) {
    return x * sigmoidf_(x);
}

// Forward GEMM: C[j][p] = act( sum_k A[k][p] * W[k][j] + b[j] )
// 128 threads: 8 p-groups (8 paths = 4 packed f32x2) x 16 j-groups (8 outputs)
// 64 MACs per 64 B of LDS per thread-k: fma pipe and smem crossbar balanced.
template<bool DOSILU>
__device__ __forceinline__ void gemm_fwd(const float* __restrict__ A,
                                         const float* __restrict__ W,
                                         const float* __restrict__ b,
                                         float* __restrict__ C, int tid)
{
    const int pg = tid & 7, jg = tid >> 3;     // jg 0..15
    const int p8 = pg * 8, j8 = jg * 8;
    ull acc[8][4];                              // [jj][pair]
#pragma unroll
    for (int a = 0; a < 8; a++)
#pragma unroll
        for (int c = 0; c < 4; c++) acc[a][c] = 0ULL;

#pragma unroll 4
    for (int k = 0; k < H; k++) {
        ulonglong2 a01 = *(const ulonglong2*)&A[k * BS + p8];
        ulonglong2 a23 = *(const ulonglong2*)&A[k * BS + p8 + 4];
        ull ap[4] = {a01.x, a01.y, a23.x, a23.y};
        float4 w0 = *(const float4*)&W[k * WS + j8];
        float4 w1 = *(const float4*)&W[k * WS + j8 + 4];
        float wv[8] = {w0.x, w0.y, w0.z, w0.w, w1.x, w1.y, w1.z, w1.w};
#pragma unroll
        for (int jj = 0; jj < 8; jj++) {
            ull wp; PACK2(wp, wv[jj], wv[jj]);
#pragma unroll
            for (int q = 0; q < 4; q++)
                FMA2(acc[jj][q], wp, ap[q]);
        }
    }

#pragma unroll
    for (int jj = 0; jj < 8; jj++) {
        float bb = b[j8 + jj];
        float r[8];
#pragma unroll
        for (int q = 0; q < 4; q++)
            UNPACK2(r[2 * q], r[2 * q + 1], acc[jj][q]);
#pragma unroll
        for (int pp = 0; pp < 8; pp++) {
            float z = r[pp] + bb;
            r[pp] = DOSILU ? siluf_(z) : z;
        }
        *(float4*)&C[(j8 + jj) * BS + p8]     = make_float4(r[0], r[1], r[2], r[3]);
        *(float4*)&C[(j8 + jj) * BS + p8 + 4] = make_float4(r[4], r[5], r[6], r[7]);
    }
}

// Backward GEMM + fused epilogue:
//   dh1[p][k] = sum_j Dz[j][p] * Wg[k][j]
//   dz1 = dh1 * silu'(z1(p,k)),  corr partials into corrp[kg][p][d]
// 128 threads: 8 p-groups x 16 k-groups. Each k-group owns STRIDED k-set
// {kg, kg+16, ..., kg+112}: within one LDS inst lanes carry consecutive kg
// (address stride WS=136 -> bank stride 8 -> conflict-free).
__device__ __forceinline__ void gemm_bwd_epi(const float* __restrict__ Dz,
                                             const float* __restrict__ Wg,
                                             const float* __restrict__ gw1s,
                                             const float* __restrict__ gb1s,
                                             const float* __restrict__ ysm,
                                             float* __restrict__ corrp, int tid)
{
    const int pg = tid & 7, kg = tid >> 3;     // kg 0..15
    const int p8 = pg * 8;
    ull acc[8][4];                              // [m][pair], k = kg + 16*m
#pragma unroll
    for (int a = 0; a < 8; a++)
#pragma unroll
        for (int c = 0; c < 4; c++) acc[a][c] = 0ULL;

#pragma unroll 4
    for (int j = 0; j < H; j++) {
        ulonglong2 a01 = *(const ulonglong2*)&Dz[j * BS + p8];
        ulonglong2 a23 = *(const ulonglong2*)&Dz[j * BS + p8 + 4];
        ull ap[4] = {a01.x, a01.y, a23.x, a23.y};
#pragma unroll
        for (int m = 0; m < 8; m++) {
            float w = Wg[(kg + 16 * m) * WS + j];
            ull wp; PACK2(wp, w, w);
#pragma unroll
            for (int q = 0; q < 4; q++)
                FMA2(acc[m][q], wp, ap[q]);
        }
    }

    // epilogue: dz1 = dh1 * silu'(z1), z1 recomputed from y
    float w0[8], w1[8], bb[8];
#pragma unroll
    for (int m = 0; m < 8; m++) {
        int k = kg + 16 * m;
        w0[m] = gw1s[k];
        w1[m] = gw1s[H + k];
        bb[m] = gb1s[k];
    }
    float dh1[8][8];
#pragma unroll
    for (int m = 0; m < 8; m++)
#pragma unroll
        for (int q = 0; q < 4; q++)
            UNPACK2(dh1[m][2 * q], dh1[m][2 * q + 1], acc[m][q]);

#pragma unroll
    for (int pp = 0; pp < 8; pp++) {
        int p = p8 + pp;
        float ya = ysm[p * 2], yb = ysm[p * 2 + 1];
        float c0 = 0.0f, c1 = 0.0f;
#pragma unroll
        for (int m = 0; m < 8; m++) {
            float z1 = fmaf(ya, w0[m], fmaf(yb, w1[m], bb[m]));
            float s  = sigmoidf_(z1);
            float spr = s * (1.0f + z1 * (1.0f - s));
            float dz1 = dh1[m][pp] * spr;
            c0 = fmaf(dz1, w0[m], c0);
            c1 = fmaf(dz1, w1[m], c1);
        }
        corrp[(kg * PPB + p) * 2]     = c0;
        corrp[(kg * PPB + p) * 2 + 1] = c1;
    }
}

extern "C" __global__ void __launch_bounds__(NTH, 1)
sde_milstein_kernel(const float* __restrict__ y0, const float* __restrict__ ts,
                    const float* __restrict__ dW,
                    const float* __restrict__ fw1, const float* __restrict__ fb1,
                    const float* __restrict__ fw2, const float* __restrict__ fb2,
                    const float* __restrict__ fw3, const float* __restrict__ fb3,
                    const float* __restrict__ gw1, const float* __restrict__ gb1,
                    const float* __restrict__ gw2, const float* __restrict__ gb2,
                    const float* __restrict__ gw3, const float* __restrict__ gb3,
                    float* __restrict__ out, int T, int NP)
{
    extern __shared__ float sm[];
    float* fw2s = sm;                      // 17408
    float* gw2s = fw2s + H * WS;           // 17408
    float* buf1 = gw2s + H * WS;           // 8704
    float* buf2 = buf1 + H * BS;           // 8704
    float* corrp = buf2 + H * BS;          // 2048
    float* fw1s = corrp + 16 * PPB * 2;    // 384   [i*128+k]
    float* fb1s = fw1s + 3 * H;            // 128
    float* fb2s = fb1s + H;                // 128
    float* fw3s = fb2s + H;                // 256   [j*2+d]
    float* fb3s = fw3s + H * 2;            // 4
    float* gw1s = fb3s + 4;                // 256   [i*128+k]
    float* gb1s = gw1s + 2 * H;            // 128
    float* gb2s = gb1s + H;                // 128
    float* gw3s = gb2s + H;                // 256   [j*2+d]
    float* gb3s = gw3s + H * 2;            // 4
    float* ysm  = gb3s + 4;                // 128   [p*2+d]
    float* f_sm = ysm + PPB * 2;           // 128
    float* g_sm = f_sm + PPB * 2;          // 128
    float* dw_sm = g_sm + PPB * 2;         // 128
    float* dr_sm = dw_sm + PPB * 2;        // 128

    const int tid = threadIdx.x;
    const int p0g = blockIdx.x * PPB;

    // ---- load weights into shared ----
    for (int i = tid; i < H * H; i += NTH) {
        int k = i >> 7, j = i & 127;
        fw2s[k * WS + j] = fw2[i];
        gw2s[k * WS + j] = gw2[i];
    }
    for (int i = tid; i < 3 * H; i += NTH) fw1s[i] = fw1[i];
    for (int i = tid; i < 2 * H; i += NTH) {
        gw1s[i] = gw1[i];
        fw3s[i] = fw3[i];
        gw3s[i] = gw3[i];
    }
    for (int i = tid; i < H; i += NTH) {
        fb1s[i] = fb1[i]; fb2s[i] = fb2[i];
        gb1s[i] = gb1[i]; gb2s[i] = gb2[i];
    }
    if (tid < 2) { fb3s[tid] = fb3[tid]; gb3s[tid] = gb3[tid]; }

    // ---- init state + write t=0 output ----
    {
        int p = tid >> 1, d = tid & 1;
        float v = y0[(size_t)(p0g) * 2 + tid];
        ysm[tid] = v;
        out[(size_t)(p0g + p) * (size_t)(T * 2) + d] = v;
    }
    __syncthreads();

    const int pA = tid & 63;     // path for elementwise-over-k phases
    const int kA = tid >> 6;     // starting k (0 or 1), step 2

    for (int t = 0; t < T - 1; ++t) {
        float dt = ts[t + 1] - ts[t];
        float sqdt = sqrtf(dt);

        // P1: drift layer1 -> buf1 = silu([y, spread] @ fw1 + fb1), transposed [k][p]
        {
            float ya = ysm[pA * 2], yb = ysm[pA * 2 + 1], yc = ya - yb;
#pragma unroll 4
            for (int k = kA; k < H; k += 2) {
                float z = fb1s[k];
                z = fmaf(ya, fw1s[k], z);
                z = fmaf(yb, fw1s[H + k], z);
                z = fmaf(yc, fw1s[2 * H + k], z);
                buf1[k * BS + pA] = siluf_(z);
            }
        }
        __syncthreads();

        // G1: h2f = silu(h1f @ fw2 + fb2) -> buf2
        gemm_fwd<true>(buf1, fw2s, fb2s, buf2, tid);
        __syncthreads();

        // P3: f = h2f @ fw3 + fb3       (one thread per (p,d))
        {
            int p = tid >> 1, d = tid & 1;
            float a0 = 0.0f, a1 = 0.0f;
#pragma unroll 8
            for (int j = 0; j < H; j += 2) {
                a0 = fmaf(buf2[j * BS + p],       fw3s[j * 2 + d],       a0);
                a1 = fmaf(buf2[(j + 1) * BS + p], fw3s[(j + 1) * 2 + d], a1);
            }
            f_sm[tid] = a0 + a1 + fb3s[d];
        }
        // P4: diffusion layer1 -> buf1 (disjoint buffer, no sync needed vs P3)
        {
            float ya = ysm[pA * 2], yb = ysm[pA * 2 + 1];
#pragma unroll 4
            for (int k = kA; k < H; k += 2) {
                float z = fmaf(ya, gw1s[k], fmaf(yb, gw1s[H + k], gb1s[k]));
                buf1[k * BS + pA] = siluf_(z);
            }
        }
        __syncthreads();

        // G2: z2g = h1g @ gw2 + gb2 (PRE-activation kept for backward) -> buf2
        gemm_fwd<false>(buf1, gw2s, gb2s, buf2, tid);
        __syncthreads();

        // P6: g = clip(softplus(raw)), Milstein cotangent draw (dual chains)
        {
            int p = tid >> 1, d = tid & 1;
            float a0 = 0.0f, a1 = 0.0f;
#pragma unroll 4
            for (int j = 0; j < H; j += 2) {
                a0 = fmaf(siluf_(buf2[j * BS + p]),       gw3s[j * 2 + d],       a0);
                a1 = fmaf(siluf_(buf2[(j + 1) * BS + p]), gw3s[(j + 1) * 2 + d], a1);
            }
            float raw = a0 + a1 + gb3s[d];
            float e  = __expf(raw);
            float sp = (raw > 15.0f) ? raw : log1pf(e);
            float g  = fminf(fmaxf(sp, 1e-4f), 5.0f);
            float dwv = dW[((size_t)t * (size_t)NP + (p0g + p)) * 2 + d] * sqdt;
            float v   = 0.5f * (dwv * dwv - dt);
            float sig = __fdividef(e, 1.0f + e);              // sigmoid(raw)
            float m   = (sp > 1e-4f && sp < 5.0f) ? 1.0f : 0.0f;
            g_sm[tid]  = g;
            dw_sm[tid] = dwv;
            dr_sm[tid] = v * g * sig * m;
        }
        __syncthreads();

        // P7: dz2 = (draw @ gw3^T) * silu'(z2g) -> buf1
        {
            float r0 = dr_sm[pA * 2], r1 = dr_sm[pA * 2 + 1];
#pragma unroll 4
            for (int k = kA; k < H; k += 2) {
                float z = buf2[k * BS + pA];
                float s = sigmoidf_(z);
                float spr = s * (1.0f + z * (1.0f - s));
                float dh2 = fmaf(r0, gw3s[k * 2], r1 * gw3s[k * 2 + 1]);
                buf1[k * BS + pA] = dh2 * spr;
            }
        }
        __syncthreads();

        // G3: dh1 = dz2 @ gw2^T, fused dz1 + corr partials -> corrp
        gemm_bwd_epi(buf1, gw2s, gw1s, gb1s, ysm, corrp, tid);
        __syncthreads();

        // P9: reduce corr, Milstein update, write output
        {
            int p = tid >> 1, d = tid & 1;
            float c0 = 0.0f, c1 = 0.0f;
#pragma unroll
            for (int kg = 0; kg < 16; kg += 2) {
                c0 += corrp[(kg * PPB + p) * 2 + d];
                c1 += corrp[((kg + 1) * PPB + p) * 2 + d];
            }
            float yn = ysm[tid] + f_sm[tid] * dt + g_sm[tid] * dw_sm[tid] + (c0 + c1);
            ysm[tid] = yn;
            out[(size_t)(p0g + p) * (size_t)(T * 2) + (size_t)(t + 1) * 2 + d] = yn;
        }
        __syncthreads();
    }
}

extern "C" void kernel_launch(void* const* d_in, const int* in_sizes, int n_in,
                              void* d_out, int out_size)
{
    const float* y0  = (const float*)d_in[0];
    const float* ts  = (const float*)d_in[1];
    const float* dW  = (const float*)d_in[2];
    const float* fw1 = (const float*)d_in[3];
    const float* fb1 = (const float*)d_in[4];
    const float* fw2 = (const float*)d_in[5];
    const float* fb2 = (const float*)d_in[6];
    const float* fw3 = (const float*)d_in[7];
    const float* fb3 = (const float*)d_in[8];
    const float* gw1 = (const float*)d_in[9];
    const float* gb1 = (const float*)d_in[10];
    const float* gw2 = (const float*)d_in[11];
    const float* gb2 = (const float*)d_in[12];
    const float* gw3 = (const float*)d_in[13];
    const float* gb3 = (const float*)d_in[14];
    float* out = (float*)d_out;

    int T  = in_sizes[1];          // 512
    int NP = in_sizes[0] / 2;      // 8192
    int nb = NP / PPB;             // 128 blocks

    cudaFuncSetAttribute(sde_milstein_kernel,
                         cudaFuncAttributeMaxDynamicSharedMemorySize, SMEM_BYTES);

    sde_milstein_kernel<<<nb, NTH, SMEM_BYTES>>>(
        y0, ts, dW, fw1, fb1, fw2, fb2, fw3, fb3,
        gw1, gb1, gw2, gb2, gw3, gb3, out, T, NP);
}